// round 1
// baseline (speedup 1.0000x reference)
#include <cuda_runtime.h>
#include <cstdint>

// Problem constants (fixed by the dataset)
#define NB    16
#define CH    256
#define LPIX  9216          // 96*96
#define NHEAD 8
#define HK    32            // CH / NHEAD
#define LT    64            // pixel tile per block
#define NLT   144           // LPIX / LT
#define XS_STRIDE 68        // 64 + 4 pad (keeps 16B row alignment, kills column conflicts)
#define WS_STRIDE 257       // 256 + 1 pad (conflict-free transposed W-tile stores)

// Scratch (allocation-free rule: __device__ globals)
__device__ float g_K[NB * CH * LPIX];            // 151 MB
__device__ float g_V[NB * CH * LPIX];            // 151 MB
__device__ float g_ctx[NB * NHEAD * HK * HK];    // normalized per-head context

// ---------------------------------------------------------------------------
// Fast exp on the FMA pipe (avoids MUFU throughput wall: 37.7M exps needed).
// exp(x) = 2^n * exp(t),  n = round(x*log2e), t = (x*log2e - n)*ln2, |t|<=0.347
// Taylor deg-5 remainder ~2.4e-6 rel. Valid for |x| < ~80 (we have |x| < ~10).
// ---------------------------------------------------------------------------
__device__ __forceinline__ float fexp(float x) {
    const float LOG2E = 1.4426950408889634f;
    const float SHIFT = 12582912.0f;             // 1.5 * 2^23
    float y = x * LOG2E;
    float z = __fadd_rn(y, SHIFT);
    int   n = __float_as_int(z) - 0x4B400000;
    float f = y - __fsub_rn(z, SHIFT);           // [-0.5, 0.5]
    float t = f * 0.6931471805599453f;
    float p = 1.0f + t * (1.0f + t * (0.5f + t * (0.16666667f +
              t * (0.041666667f + t * 0.0083333333f))));
    return __int_as_float((n + 127) << 23) * p;
}

// ---------------------------------------------------------------------------
// Shared GEMM tile: acc[8][8] += W(256xCH row-major, k-tile staged via Ws) @ Bs
// Block = 256 threads, output tile 256(cout) x 64(pix), BK = 32.
// Ws is stored transposed [k][o] with stride 257 -> conflict-free stores,
// broadcast-friendly compute reads. Bs rows are stride-68, 16B aligned.
// ---------------------------------------------------------------------------
__device__ __forceinline__ void gemm_tile_256x64(
    const float* __restrict__ W, float* Ws, const float* Bs,
    int ob, int pb, int tid, float acc[8][8])
{
    for (int kt = 0; kt < CH; kt += 32) {
        __syncthreads();                         // protect Ws from prior readers
        for (int i = tid; i < CH * 32; i += 256) {
            int k = i & 31;                      // lanes -> consecutive k: coalesced LDG
            int o = i >> 5;
            Ws[k * WS_STRIDE + o] = W[o * CH + kt + k];   // (k+o)%32 distinct: no conflicts
        }
        __syncthreads();
        #pragma unroll 4
        for (int kk = 0; kk < 32; ++kk) {
            float a[8];
            #pragma unroll
            for (int i = 0; i < 8; ++i) a[i] = Ws[kk * WS_STRIDE + ob + i];
            const float* brow = &Bs[(kt + kk) * XS_STRIDE + pb];
            float4 b0 = *reinterpret_cast<const float4*>(brow);
            float4 b1 = *reinterpret_cast<const float4*>(brow + 4);
            float b[8] = {b0.x, b0.y, b0.z, b0.w, b1.x, b1.y, b1.z, b1.w};
            #pragma unroll
            for (int i = 0; i < 8; ++i)
                #pragma unroll
                for (int j = 0; j < 8; ++j)
                    acc[i][j] += a[i] * b[j];
        }
    }
    __syncthreads();                             // next user may overwrite Ws/Bs
}

// ---------------------------------------------------------------------------
// Kernel 1: K = Wk@context + bk, V = Wv@context + bv.
// One block = one 64-pixel tile of one batch; context tile loaded ONCE into
// smem and reused for both projections. 2 blocks/SM.
// ---------------------------------------------------------------------------
__global__ void __launch_bounds__(256, 2)
proj_kv_kernel(const float* __restrict__ ctxt,
               const float* __restrict__ Wk, const float* __restrict__ bk,
               const float* __restrict__ Wv, const float* __restrict__ bv)
{
    const int lt = blockIdx.x, n = blockIdx.y;
    const int l0 = lt * LT;
    extern __shared__ float smem[];
    float* Xs = smem;                            // [256][68]
    float* Ws = smem + CH * XS_STRIDE;           // [32][257]
    const int tid = threadIdx.x;

    const float* src = ctxt + (size_t)n * CH * LPIX + l0;
    for (int i = tid; i < CH * LT / 4; i += 256) {
        int c  = i >> 4;
        int j4 = (i & 15) << 2;
        *reinterpret_cast<float4*>(&Xs[c * XS_STRIDE + j4]) =
            *reinterpret_cast<const float4*>(src + (size_t)c * LPIX + j4);
    }
    __syncthreads();

    const int tx = tid & 7, ty = tid >> 3;
    const int ob = ty * 8, pb = tx * 8;

    #pragma unroll 1
    for (int mat = 0; mat < 2; ++mat) {
        const float* W    = mat ? Wv : Wk;
        const float* bias = mat ? bv : bk;
        float* outp = (mat ? g_V : g_K) + (size_t)n * CH * LPIX + l0;

        float acc[8][8];
        #pragma unroll
        for (int i = 0; i < 8; ++i)
            #pragma unroll
            for (int j = 0; j < 8; ++j) acc[i][j] = 0.0f;

        gemm_tile_256x64(W, Ws, Xs, ob, pb, tid, acc);

        #pragma unroll
        for (int i = 0; i < 8; ++i) {
            float bo = __ldg(&bias[ob + i]);
            float* orow = outp + (size_t)(ob + i) * LPIX + pb;
            float4 r0 = make_float4(acc[i][0] + bo, acc[i][1] + bo,
                                    acc[i][2] + bo, acc[i][3] + bo);
            float4 r1 = make_float4(acc[i][4] + bo, acc[i][5] + bo,
                                    acc[i][6] + bo, acc[i][7] + bo);
            *reinterpret_cast<float4*>(orow)     = r0;
            *reinterpret_cast<float4*>(orow + 4) = r1;
        }
    }
}

// ---------------------------------------------------------------------------
// Kernel 2: per (n, head) block computes ctx[32][32] = softmax_L(K) @ V^T in
// ONE pass (normalize by row-sum of exp at the end). 256 threads, each owns a
// 2x2 (k,v) micro-tile; K/V streamed through smem in 128-wide chunks.
// ---------------------------------------------------------------------------
__global__ void ctx_kernel()
{
    const int h = blockIdx.x, n = blockIdx.y;
    __shared__ float eKs[HK * 132];              // stride 132: aligned + conflict-free
    __shared__ float Vs [HK * 132];
    __shared__ float ssum[HK];

    const int tid = threadIdx.x;
    const int kg = tid >> 4, vg = tid & 15;
    const int k0 = kg * 2,  v0 = vg * 2;

    float a00 = 0.f, a01 = 0.f, a10 = 0.f, a11 = 0.f;
    float s0 = 0.f, s1 = 0.f;

    const float* Kp = g_K + ((size_t)n * CH + h * HK) * LPIX;
    const float* Vp = g_V + ((size_t)n * CH + h * HK) * LPIX;

    for (int l0 = 0; l0 < LPIX; l0 += 128) {
        __syncthreads();
        for (int i = tid; i < HK * 128; i += 256) {
            int r = i >> 7, j = i & 127;
            eKs[r * 132 + j] = fexp(Kp[(size_t)r * LPIX + l0 + j]);
            Vs [r * 132 + j] =       Vp[(size_t)r * LPIX + l0 + j];
        }
        __syncthreads();
        #pragma unroll 4
        for (int j = 0; j < 128; j += 4) {
            float4 e0 = *reinterpret_cast<const float4*>(&eKs[ k0      * 132 + j]);
            float4 e1 = *reinterpret_cast<const float4*>(&eKs[(k0 + 1) * 132 + j]);
            float4 w0 = *reinterpret_cast<const float4*>(&Vs [ v0      * 132 + j]);
            float4 w1 = *reinterpret_cast<const float4*>(&Vs [(v0 + 1) * 132 + j]);
            a00 += e0.x*w0.x + e0.y*w0.y + e0.z*w0.z + e0.w*w0.w;
            a01 += e0.x*w1.x + e0.y*w1.y + e0.z*w1.z + e0.w*w1.w;
            a10 += e1.x*w0.x + e1.y*w0.y + e1.z*w0.z + e1.w*w0.w;
            a11 += e1.x*w1.x + e1.y*w1.y + e1.z*w1.z + e1.w*w1.w;
            if (vg == 0) {                       // one thread per k-pair owns row sums
                s0 += e0.x + e0.y + e0.z + e0.w;
                s1 += e1.x + e1.y + e1.z + e1.w;
            }
        }
    }
    if (vg == 0) { ssum[k0] = s0; ssum[k0 + 1] = s1; }
    __syncthreads();

    float i0 = 1.0f / ssum[k0];
    float i1 = 1.0f / ssum[k0 + 1];
    float* cg = g_ctx + (size_t)(n * NHEAD + h) * HK * HK;
    cg[ k0      * HK + v0    ] = a00 * i0;
    cg[ k0      * HK + v0 + 1] = a01 * i0;
    cg[(k0 + 1) * HK + v0    ] = a10 * i1;
    cg[(k0 + 1) * HK + v0 + 1] = a11 * i1;
}

// ---------------------------------------------------------------------------
// Kernel 3 (fully fused tail): per 64-pixel tile:
//   Q = Wq@x + bq  ->  per-(head,pixel) softmax over 32 channels
//   agg = ctx^T @ softmax(Q)  (in-place in Qs)
//   out = Wr@agg + br + x     (residual comes straight from the Xs tile)
// Input read once, output written once. 1 block/SM (205 KB smem).
// ---------------------------------------------------------------------------
__global__ void __launch_bounds__(256, 1)
att_out_kernel(const float* __restrict__ input,
               const float* __restrict__ Wq, const float* __restrict__ bq,
               const float* __restrict__ Wr, const float* __restrict__ br,
               float* __restrict__ out)
{
    const int lt = blockIdx.x, n = blockIdx.y;
    const int l0 = lt * LT;
    extern __shared__ float smem[];
    float* Xs = smem;                              // [256][68] input tile (kept for residual)
    float* Qs = Xs + CH * XS_STRIDE;               // [256][68] Q, then agg (in place)
    float* Ws = Qs + CH * XS_STRIDE;               // [32][257]
    float* Cs = Ws + 32 * WS_STRIDE;               // [8][32][32] normalized ctx
    const int tid = threadIdx.x;

    const float* ctxg = g_ctx + (size_t)n * NHEAD * HK * HK;
    for (int i = tid; i < NHEAD * HK * HK / 4; i += 256)
        reinterpret_cast<float4*>(Cs)[i] = reinterpret_cast<const float4*>(ctxg)[i];

    const float* xin = input + (size_t)n * CH * LPIX + l0;
    for (int i = tid; i < CH * LT / 4; i += 256) {
        int c  = i >> 4;
        int j4 = (i & 15) << 2;
        *reinterpret_cast<float4*>(&Xs[c * XS_STRIDE + j4]) =
            *reinterpret_cast<const float4*>(xin + (size_t)c * LPIX + j4);
    }
    __syncthreads();

    const int tx = tid & 7, ty = tid >> 3;
    const int ob = ty * 8, pb = tx * 8;

    // ---- GEMM 1: Qs = Wq @ Xs + bq ----
    {
        float acc[8][8];
        #pragma unroll
        for (int i = 0; i < 8; ++i)
            #pragma unroll
            for (int j = 0; j < 8; ++j) acc[i][j] = 0.0f;
        gemm_tile_256x64(Wq, Ws, Xs, ob, pb, tid, acc);
        #pragma unroll
        for (int i = 0; i < 8; ++i) {
            float bo = __ldg(&bq[ob + i]);
            float* qrow = &Qs[(ob + i) * XS_STRIDE + pb];
            #pragma unroll
            for (int j = 0; j < 8; ++j) qrow[j] = acc[i][j] + bo;
        }
    }
    __syncthreads();

    // ---- channel-softmax + ctx apply (in place, each thread owns 2 columns) ----
    #pragma unroll
    for (int r = 0; r < 2; ++r) {
        int item = tid + r * 256;                // 512 = 8 heads * 64 pixels
        int h = item >> 6, pix = item & 63;
        float q[HK];
        float s = 0.0f;
        #pragma unroll
        for (int k = 0; k < HK; ++k) {
            q[k] = fexp(Qs[(h * HK + k) * XS_STRIDE + pix]);
            s += q[k];
        }
        float inv = 1.0f / s;
        const float* ch = Cs + h * HK * HK;      // [k][v]
        #pragma unroll
        for (int vgp = 0; vgp < HK / 4; ++vgp) {
            float4 a = make_float4(0.f, 0.f, 0.f, 0.f);
            #pragma unroll 8
            for (int k = 0; k < HK; ++k) {
                float4 cv = *reinterpret_cast<const float4*>(&ch[k * HK + vgp * 4]);
                a.x += cv.x * q[k]; a.y += cv.y * q[k];
                a.z += cv.z * q[k]; a.w += cv.w * q[k];
            }
            Qs[(h * HK + vgp * 4 + 0) * XS_STRIDE + pix] = a.x * inv;
            Qs[(h * HK + vgp * 4 + 1) * XS_STRIDE + pix] = a.y * inv;
            Qs[(h * HK + vgp * 4 + 2) * XS_STRIDE + pix] = a.z * inv;
            Qs[(h * HK + vgp * 4 + 3) * XS_STRIDE + pix] = a.w * inv;
        }
    }
    __syncthreads();

    // ---- GEMM 2: out = Wr @ Qs(agg) + br + Xs(residual) ----
    {
        float acc[8][8];
        #pragma unroll
        for (int i = 0; i < 8; ++i)
            #pragma unroll
            for (int j = 0; j < 8; ++j) acc[i][j] = 0.0f;
        gemm_tile_256x64(Wr, Ws, Qs, ob, pb, tid, acc);
        #pragma unroll
        for (int i = 0; i < 8; ++i) {
            float bo = __ldg(&br[ob + i]);
            const float* xr = &Xs[(ob + i) * XS_STRIDE + pb];
            float* orow = out + (size_t)(n * CH + ob + i) * LPIX + l0 + pb;
            float4 r0 = make_float4(acc[i][0] + bo + xr[0], acc[i][1] + bo + xr[1],
                                    acc[i][2] + bo + xr[2], acc[i][3] + bo + xr[3]);
            float4 r1 = make_float4(acc[i][4] + bo + xr[4], acc[i][5] + bo + xr[5],
                                    acc[i][6] + bo + xr[6], acc[i][7] + bo + xr[7]);
            *reinterpret_cast<float4*>(orow)     = r0;
            *reinterpret_cast<float4*>(orow + 4) = r1;
        }
    }
}

// ---------------------------------------------------------------------------
extern "C" void kernel_launch(void* const* d_in, const int* in_sizes, int n_in,
                              void* d_out, int out_size)
{
    (void)in_sizes; (void)n_in; (void)out_size;
    const float* input_   = (const float*)d_in[0];
    const float* context_ = (const float*)d_in[1];
    const float* Wk = (const float*)d_in[2];
    const float* bk = (const float*)d_in[3];
    const float* Wq = (const float*)d_in[4];
    const float* bq = (const float*)d_in[5];
    const float* Wv = (const float*)d_in[6];
    const float* bv = (const float*)d_in[7];
    const float* Wr = (const float*)d_in[8];
    const float* br = (const float*)d_in[9];
    float* out = (float*)d_out;

    const int SMEM1 = (CH * XS_STRIDE + 32 * WS_STRIDE) * (int)sizeof(float);            // 102,528
    const int SMEM3 = (2 * CH * XS_STRIDE + 32 * WS_STRIDE + NHEAD * HK * HK)
                      * (int)sizeof(float);                                              // 204,928
    cudaFuncSetAttribute(proj_kv_kernel, cudaFuncAttributeMaxDynamicSharedMemorySize, SMEM1);
    cudaFuncSetAttribute(att_out_kernel, cudaFuncAttributeMaxDynamicSharedMemorySize, SMEM3);

    proj_kv_kernel<<<dim3(NLT, NB), 256, SMEM1>>>(context_, Wk, bk, Wv, bv);
    ctx_kernel   <<<dim3(NHEAD, NB), 256>>>();
    att_out_kernel<<<dim3(NLT, NB), 256, SMEM3>>>(input_, Wq, bq, Wr, br, out);
}